// round 2
// baseline (speedup 1.0000x reference)
#include <cuda_runtime.h>
#include <math_constants.h>
#include <cstdint>

#define B_   16
#define L_   18
#define SQ_  256
#define H_   2560
#define R_   256
#define D_   2048
#define C_   32
#define TOPK_ 16

// Scratch (no allocations allowed — __device__ globals)
__device__ unsigned int g_qenc[B_ * L_ * R_];
__device__ float        g_qvec[B_ * L_ * R_];
__device__ float        g_scores[B_ * D_];

// Order-preserving float <-> uint encoding for atomicMax
__device__ __forceinline__ unsigned enc_f(float f) {
    unsigned u = __float_as_uint(f);
    return (u & 0x80000000u) ? ~u : (u | 0x80000000u);
}
__device__ __forceinline__ float dec_f(unsigned u) {
    unsigned b = (u & 0x80000000u) ? (u & 0x7FFFFFFFu) : ~u;
    return __uint_as_float(b);
}

// ---------------------------------------------------------------------------
// Kernel 0: reset encoded-max buffer (0 == encoding below every finite float)
// ---------------------------------------------------------------------------
__global__ void init_kernel() {
    g_qenc[blockIdx.x * 256 + threadIdx.x] = 0u;
}

// ---------------------------------------------------------------------------
// Kernel 1: projection GEMM + max-pool over s.
// Per (b,l): C[s,r] = sum_h qhs[b,l,s,h] * wq[l,r,h]   (both K-major: A·B^T)
// Tiles: 128x128x(K=32 steps), 256 threads, 8x8 microtile.
// Epilogue: per-thread max over its 8 s-rows, then global atomicMax (encoded).
// ---------------------------------------------------------------------------
__global__ __launch_bounds__(256, 2)
void proj_kernel(const float* __restrict__ qhs, const float* __restrict__ wq) {
    const int bl = blockIdx.x;
    const int b  = bl / L_;
    const int l  = bl % L_;
    const int sT = blockIdx.y;   // 0..1 (s tile of 128)
    const int rT = blockIdx.z;   // 0..1 (r tile of 128)

    const float* Ag = qhs + ((size_t)(b * L_ + l) * SQ_ + (size_t)sT * 128) * H_;
    const float* Bg = wq  + ((size_t)l * R_ + (size_t)rT * 128) * H_;

    __shared__ float As[32][132];   // transposed [k][row], padded
    __shared__ float Bs[32][132];

    const int tid = threadIdx.x;
    const int tx  = tid & 15;       // 0..15 -> r micro
    const int ty  = tid >> 4;       // 0..15 -> s micro

    float acc[8][8];
#pragma unroll
    for (int i = 0; i < 8; i++)
#pragma unroll
        for (int j = 0; j < 8; j++) acc[i][j] = 0.0f;

    for (int k0 = 0; k0 < H_; k0 += 32) {
#pragma unroll
        for (int i = 0; i < 4; i++) {
            int q   = tid + i * 256;        // 0..1023 quad id
            int row = q >> 3;               // 0..127
            int kq  = (q & 7) << 2;         // 0,4,...,28
            float4 va = *(const float4*)(Ag + (size_t)row * H_ + k0 + kq);
            As[kq + 0][row] = va.x; As[kq + 1][row] = va.y;
            As[kq + 2][row] = va.z; As[kq + 3][row] = va.w;
            float4 vb = *(const float4*)(Bg + (size_t)row * H_ + k0 + kq);
            Bs[kq + 0][row] = vb.x; Bs[kq + 1][row] = vb.y;
            Bs[kq + 2][row] = vb.z; Bs[kq + 3][row] = vb.w;
        }
        __syncthreads();

#pragma unroll
        for (int kk = 0; kk < 32; kk++) {
            float a[8], bb[8];
            *(float4*)&a[0]  = *(const float4*)&As[kk][ty * 8];
            *(float4*)&a[4]  = *(const float4*)&As[kk][ty * 8 + 4];
            *(float4*)&bb[0] = *(const float4*)&Bs[kk][tx * 8];
            *(float4*)&bb[4] = *(const float4*)&Bs[kk][tx * 8 + 4];
#pragma unroll
            for (int i = 0; i < 8; i++)
#pragma unroll
                for (int j = 0; j < 8; j++)
                    acc[i][j] = fmaf(a[i], bb[j], acc[i][j]);
        }
        __syncthreads();
    }

    // Max over this thread's 8 s-rows, combine across blocks via atomicMax.
    unsigned* qe = g_qenc + (size_t)(b * L_ + l) * R_ + rT * 128;
#pragma unroll
    for (int j = 0; j < 8; j++) {
        float m = acc[0][j];
#pragma unroll
        for (int i = 1; i < 8; i++) m = fmaxf(m, acc[i][j]);
        atomicMax(&qe[tx * 8 + j], enc_f(m));
    }
}

// ---------------------------------------------------------------------------
// Kernel 2: decode + L2-normalize q_vec over R (one block per (b,l))
// ---------------------------------------------------------------------------
__global__ void norm_kernel() {
    const int blk = blockIdx.x;        // b*L + l
    const int t   = threadIdx.x;       // 0..255 == r
    float v = dec_f(g_qenc[blk * R_ + t]);
    float s = v * v;
#pragma unroll
    for (int o = 16; o > 0; o >>= 1) s += __shfl_xor_sync(0xffffffffu, s, o);
    __shared__ float ws[8];
    if ((t & 31) == 0) ws[t >> 5] = s;
    __syncthreads();
    float tot = 0.0f;
#pragma unroll
    for (int i = 0; i < 8; i++) tot += ws[i];
    float nrm = sqrtf(tot);
    g_qvec[blk * R_ + t] = v / fmaxf(nrm, 1e-12f);
}

// ---------------------------------------------------------------------------
// Kernel 3: doc scoring. One block per doc d. 256 threads:
//   warp w (0..7) handles chunks c = 4w + (lane>>3); bg = lane&7 handles
//   b0 = bg and b1 = bg+8. Per layer l: dot(k_c, q_b) over R, plus ||k_c||,
//   normalize, max over c (shuffles + smem), accumulate mean over l.
// ---------------------------------------------------------------------------
__global__ __launch_bounds__(256, 4)
void doc_kernel(const float* __restrict__ dkeys) {
    const int d    = blockIdx.x;
    const int tid  = threadIdx.x;
    const int w    = tid >> 5;
    const int lane = tid & 31;
    const int c    = w * 4 + (lane >> 3);
    const int bg   = lane & 7;

    __shared__ float q_s[B_ * 260];     // padded stride 260 -> conflict-free
    __shared__ float wmax[8][16];

    float acc = 0.0f;

    for (int l = 0; l < L_; l++) {
        for (int idx = tid; idx < B_ * R_; idx += 256) {
            int bb = idx >> 8, r = idx & 255;
            q_s[bb * 260 + r] = g_qvec[(bb * L_ + l) * R_ + r];
        }
        __syncthreads();

        const float4* kp = (const float4*)(dkeys +
            (((size_t)d * L_ + l) * C_ + c) * R_);
        const float4* q0 = (const float4*)&q_s[bg * 260];
        const float4* q1 = (const float4*)&q_s[(bg + 8) * 260];

        float dot0 = 0.0f, dot1 = 0.0f, nn = 0.0f;
#pragma unroll 8
        for (int r4 = 0; r4 < 64; r4++) {
            float4 k = __ldg(&kp[r4]);
            float4 a = q0[r4];
            float4 q = q1[r4];
            dot0 = fmaf(k.x, a.x, dot0); dot0 = fmaf(k.y, a.y, dot0);
            dot0 = fmaf(k.z, a.z, dot0); dot0 = fmaf(k.w, a.w, dot0);
            dot1 = fmaf(k.x, q.x, dot1); dot1 = fmaf(k.y, q.y, dot1);
            dot1 = fmaf(k.z, q.z, dot1); dot1 = fmaf(k.w, q.w, dot1);
            nn   = fmaf(k.x, k.x, nn);   nn   = fmaf(k.y, k.y, nn);
            nn   = fmaf(k.z, k.z, nn);   nn   = fmaf(k.w, k.w, nn);
        }
        float inv = 1.0f / fmaxf(sqrtf(nn), 1e-12f);
        float s0 = dot0 * inv;
        float s1 = dot1 * inv;
        // max over the warp's 4 chunks (c_sub = lane bits 3..4)
        s0 = fmaxf(s0, __shfl_xor_sync(0xffffffffu, s0, 8));
        s0 = fmaxf(s0, __shfl_xor_sync(0xffffffffu, s0, 16));
        s1 = fmaxf(s1, __shfl_xor_sync(0xffffffffu, s1, 8));
        s1 = fmaxf(s1, __shfl_xor_sync(0xffffffffu, s1, 16));
        if (lane < 8) { wmax[w][lane] = s0; wmax[w][lane + 8] = s1; }
        __syncthreads();
        if (tid < 16) {
            float mx = wmax[0][tid];
#pragma unroll
            for (int ww = 1; ww < 8; ww++) mx = fmaxf(mx, wmax[ww][tid]);
            acc += mx;
        }
        __syncthreads();
    }
    if (tid < 16) g_scores[tid * D_ + d] = acc * (1.0f / (float)L_);
}

// ---------------------------------------------------------------------------
// Kernel 4: exact top-16 (descending, lower index wins ties — jax semantics).
// One block per b. Scores first half of d_out, indices (as float) second half.
// ---------------------------------------------------------------------------
__global__ void topk_kernel(float* __restrict__ out, int half) {
    const int b = blockIdx.x;
    const int t = threadIdx.x;
    __shared__ float sv[D_];
    __shared__ float rv[256];
    __shared__ int   ri[256];

    for (int i = t; i < D_; i += 256) sv[i] = g_scores[b * D_ + i];
    __syncthreads();

    for (int k = 0; k < TOPK_; k++) {
        float bv = -CUDART_INF_F;
        int   bi = 0x7fffffff;
        for (int i = t; i < D_; i += 256) {
            float v = sv[i];
            if (v > bv || (v == bv && i < bi)) { bv = v; bi = i; }
        }
        rv[t] = bv; ri[t] = bi;
        __syncthreads();
        for (int s = 128; s > 0; s >>= 1) {
            if (t < s) {
                float ov = rv[t + s]; int oi = ri[t + s];
                if (ov > rv[t] || (ov == rv[t] && oi < ri[t])) {
                    rv[t] = ov; ri[t] = oi;
                }
            }
            __syncthreads();
        }
        if (t == 0) {
            out[b * TOPK_ + k]        = rv[0];
            out[half + b * TOPK_ + k] = (float)ri[0];
            sv[ri[0]] = -CUDART_INF_F;
        }
        __syncthreads();
    }
}

extern "C" void kernel_launch(void* const* d_in, const int* in_sizes, int n_in,
                              void* d_out, int out_size) {
    const float* qhs = (const float*)d_in[0];
    const float* wq  = (const float*)d_in[1];
    const float* dk  = (const float*)d_in[2];
    float* out = (float*)d_out;

    init_kernel<<<B_ * L_, 256>>>();
    dim3 g1(B_ * L_, 2, 2);
    proj_kernel<<<g1, 256>>>(qhs, wq);
    norm_kernel<<<B_ * L_, 256>>>();
    doc_kernel<<<D_, 256>>>(dk);
    topk_kernel<<<B_, 256>>>(out, out_size / 2);
}

// round 4
// speedup vs baseline: 1.0966x; 1.0966x over previous
#include <cuda_runtime.h>
#include <math_constants.h>
#include <cstdint>

#define B_   16
#define L_   18
#define SQ_  256
#define H_   2560
#define R_   256
#define D_   2048
#define C_   32
#define TOPK_ 16

// ---------------- scratch (no allocs allowed) ----------------
__device__ unsigned int g_qenc[B_ * L_ * R_];
__device__ float        g_qvec[B_ * L_ * R_];
__device__ float        g_scores[B_ * D_];

// Order-preserving float <-> uint encoding for atomicMax
__device__ __forceinline__ unsigned enc_f(float f) {
    unsigned u = __float_as_uint(f);
    return (u & 0x80000000u) ? ~u : (u | 0x80000000u);
}
__device__ __forceinline__ float dec_f(unsigned u) {
    unsigned b = (u & 0x80000000u) ? (u & 0x7FFFFFFFu) : ~u;
    return __uint_as_float(b);
}

__device__ __forceinline__ float tf32_rnd(float x) {
    uint32_t r;
    asm("cvt.rna.tf32.f32 %0, %1;" : "=r"(r) : "f"(x));
    return __uint_as_float(r);
}

#define MMA_TF32(Cv, Av, Bv)                                                   \
    asm volatile("mma.sync.aligned.m16n8k8.row.col.f32.tf32.tf32.f32 "         \
                 "{%0,%1,%2,%3}, {%4,%5,%6,%7}, {%8,%9}, {%0,%1,%2,%3};"       \
                 : "+f"(Cv[0]), "+f"(Cv[1]), "+f"(Cv[2]), "+f"(Cv[3])          \
                 : "r"(Av[0]), "r"(Av[1]), "r"(Av[2]), "r"(Av[3]),             \
                   "r"(Bv[0]), "r"(Bv[1]))

// ---------------------------------------------------------------------------
// Kernel 0: reset encoded-max buffer
// ---------------------------------------------------------------------------
__global__ void init_kernel() {
    g_qenc[blockIdx.x * 256 + threadIdx.x] = 0u;
}

// ---------------------------------------------------------------------------
// proj_kernel: per (b,l): C[s,r] = sum_h qhs[b,l,s,h] * wq[l,r,h]
// mma.sync tf32, 3-pass fp32 split. Block tile 128(s) x 128(r), K-stage 32.
// smem written in FRAGMENT ORDER: A lane-vectors of 4 floats (LDS.128),
// B lane-vectors of 2 floats (LDS.64). Epilogue: max over s + atomicMax.
// ---------------------------------------------------------------------------
#define KSTAGE    32
#define NSTAGES   (H_ / KSTAGE)      // 80
// floats per stage: AH 4096, AL 4096, BH 4096, BL 4096 = 16384 floats = 64KB
#define STG_F     16384
#define PROJ_SMEM (2 * STG_F * 4)    // 128 KB

__global__ __launch_bounds__(256, 1)
void proj_kernel(const float* __restrict__ qhs, const float* __restrict__ wq) {
    extern __shared__ float sm[];
    const int tid  = threadIdx.x;
    const int lane = tid & 31;
    const int warp = tid >> 5;
    const int wm   = warp >> 2;   // 0..1  (s 64-row half)
    const int wn   = warp & 3;    // 0..3  (r 32-col quarter)

    const int bl = blockIdx.x;          // b*L + l
    const int sT = blockIdx.y;          // 0..1
    const int rT = blockIdx.z;          // 0..1
    const int l  = bl % L_;

    const float* Ag = qhs + ((size_t)bl * SQ_ + (size_t)sT * 128) * H_;
    const float* Bg = wq  + ((size_t)l * R_ + (size_t)rT * 128) * H_;

    float acc[4][4][4];
#pragma unroll
    for (int i = 0; i < 4; i++)
#pragma unroll
        for (int j = 0; j < 4; j++)
#pragma unroll
            for (int k = 0; k < 4; k++) acc[i][j][k] = 0.0f;

    float4 pa[4], pb[4];

    // global prefetch of one K-stage into registers
    auto ldst = [&](int k0, float4* a, float4* b) {
#pragma unroll
        for (int i = 0; i < 4; i++) {
            int ch  = tid + i * 256;       // 0..1023
            int row = ch >> 3;
            int k4  = (ch & 7) << 2;
            a[i] = *(const float4*)(Ag + (size_t)row * H_ + k0 + k4);
            b[i] = *(const float4*)(Bg + (size_t)row * H_ + k0 + k4);
        }
    };

    // split-convert + store one stage to smem in fragment order
    auto store_stage = [&](int s, const float4* a, const float4* b) {
        float* AH = sm + s * STG_F;
        float* AL = AH + 4096;
        float* BH = AH + 8192;
        float* BL = AH + 12288;
#pragma unroll
        for (int i = 0; i < 4; i++) {
            int ch  = tid + i * 256;
            int row = ch >> 3;
            int k4  = (ch & 7) << 2;
            int ks  = k4 >> 3;
            int khf = (k4 >> 2) & 1;
            // ---- A: mt tiles of 16 rows ----
            {
                int mt = row >> 4, r16 = row & 15;
                int base = ((mt * 4 + ks) * 32 + (r16 & 7) * 4) * 4
                         + (r16 >> 3) + 2 * khf;
                const float* v = (const float*)&a[i];
#pragma unroll
                for (int e = 0; e < 4; e++) {
                    float h = tf32_rnd(v[e]);
                    AH[base + e * 4] = h;
                    AL[base + e * 4] = tf32_rnd(v[e] - h);
                }
            }
            // ---- B: nt tiles of 8 rows ----
            {
                int nt = row >> 3, n8 = row & 7;
                int base = ((nt * 4 + ks) * 32 + n8 * 4) * 2 + khf;
                const float* v = (const float*)&b[i];
#pragma unroll
                for (int e = 0; e < 4; e++) {
                    float h = tf32_rnd(v[e]);
                    BH[base + e * 2] = h;
                    BL[base + e * 2] = tf32_rnd(v[e] - h);
                }
            }
        }
    };

    ldst(0, pa, pb);
    store_stage(0, pa, pb);
    __syncthreads();

    for (int t = 0; t < NSTAGES; t++) {
        const int s = t & 1;
        if (t + 1 < NSTAGES) ldst((t + 1) * KSTAGE, pa, pb);

        const float* AH = sm + s * STG_F;
        const float* AL = AH + 4096;
        const float* BH = AH + 8192;
        const float* BL = AH + 12288;

#pragma unroll
        for (int ks = 0; ks < 4; ks++) {
            uint32_t ah[4][4], al[4][4], bh[4][2], bl4[4][2];
#pragma unroll
            for (int mt = 0; mt < 4; mt++) {
                int mtg = wm * 4 + mt;
                float4 th = *(const float4*)(AH + ((mtg * 4 + ks) * 32 + lane) * 4);
                float4 tl = *(const float4*)(AL + ((mtg * 4 + ks) * 32 + lane) * 4);
                ah[mt][0] = __float_as_uint(th.x); ah[mt][1] = __float_as_uint(th.y);
                ah[mt][2] = __float_as_uint(th.z); ah[mt][3] = __float_as_uint(th.w);
                al[mt][0] = __float_as_uint(tl.x); al[mt][1] = __float_as_uint(tl.y);
                al[mt][2] = __float_as_uint(tl.z); al[mt][3] = __float_as_uint(tl.w);
            }
#pragma unroll
            for (int nt = 0; nt < 4; nt++) {
                int ntg = wn * 4 + nt;
                float2 th = *(const float2*)(BH + ((ntg * 4 + ks) * 32 + lane) * 2);
                float2 tl = *(const float2*)(BL + ((ntg * 4 + ks) * 32 + lane) * 2);
                bh[nt][0]  = __float_as_uint(th.x); bh[nt][1]  = __float_as_uint(th.y);
                bl4[nt][0] = __float_as_uint(tl.x); bl4[nt][1] = __float_as_uint(tl.y);
            }
#pragma unroll
            for (int mt = 0; mt < 4; mt++)
#pragma unroll
                for (int nt = 0; nt < 4; nt++) MMA_TF32(acc[mt][nt], ah[mt], bh[nt]);
#pragma unroll
            for (int mt = 0; mt < 4; mt++)
#pragma unroll
                for (int nt = 0; nt < 4; nt++) MMA_TF32(acc[mt][nt], ah[mt], bl4[nt]);
#pragma unroll
            for (int mt = 0; mt < 4; mt++)
#pragma unroll
                for (int nt = 0; nt < 4; nt++) MMA_TF32(acc[mt][nt], al[mt], bh[nt]);
        }

        if (t + 1 < NSTAGES) store_stage(s ^ 1, pa, pb);
        __syncthreads();
    }

    // ---- epilogue: max over s rows, reduce over lane/4, atomicMax ----
    unsigned* qe = g_qenc + (size_t)bl * R_ + rT * 128 + wn * 32;
#pragma unroll
    for (int nt = 0; nt < 4; nt++) {
        float v0 = -CUDART_INF_F, v1 = -CUDART_INF_F;
#pragma unroll
        for (int mt = 0; mt < 4; mt++) {
            v0 = fmaxf(v0, fmaxf(acc[mt][nt][0], acc[mt][nt][2]));
            v1 = fmaxf(v1, fmaxf(acc[mt][nt][1], acc[mt][nt][3]));
        }
#pragma unroll
        for (int o = 4; o < 32; o <<= 1) {
            v0 = fmaxf(v0, __shfl_xor_sync(0xffffffffu, v0, o));
            v1 = fmaxf(v1, __shfl_xor_sync(0xffffffffu, v1, o));
        }
        if (lane < 4) {
            atomicMax(&qe[nt * 8 + lane * 2 + 0], enc_f(v0));
            atomicMax(&qe[nt * 8 + lane * 2 + 1], enc_f(v1));
        }
    }
}

// ---------------------------------------------------------------------------
// norm_kernel: decode + L2-normalize q over R (one block per (b,l))
// ---------------------------------------------------------------------------
__global__ void norm_kernel() {
    const int blk = blockIdx.x;
    const int t = threadIdx.x;
    float v = dec_f(g_qenc[blk * R_ + t]);
    float s = v * v;
#pragma unroll
    for (int o = 16; o > 0; o >>= 1) s += __shfl_xor_sync(0xffffffffu, s, o);
    __shared__ float ws[8];
    if ((t & 31) == 0) ws[t >> 5] = s;
    __syncthreads();
    float tot = 0.0f;
#pragma unroll
    for (int i = 0; i < 8; i++) tot += ws[i];
    g_qvec[blk * R_ + t] = v / fmaxf(sqrtf(tot), 1e-12f);
}

// ---------------------------------------------------------------------------
// doc_kernel: cp.async-staged k + q tiles, double-buffered per layer.
// ---------------------------------------------------------------------------
#define K_STAGE_F  (C_ * 260)
#define Q_STAGE_F  (B_ * 260)
#define STAGE_F    (K_STAGE_F + Q_STAGE_F)
#define DOC_SMEM   (2 * STAGE_F * 4 + 512)

__device__ __forceinline__ uint32_t smem_u32(const void* p) {
    uint32_t a;
    asm("{ .reg .u64 t; cvta.to.shared.u64 t, %1; cvt.u32.u64 %0, t; }"
        : "=r"(a) : "l"(p));
    return a;
}
__device__ __forceinline__ void cpa16(uint32_t saddr, const void* g) {
    asm volatile("cp.async.cg.shared.global [%0], [%1], 16;" :: "r"(saddr), "l"(g));
}
__device__ __forceinline__ void cpa_commit() { asm volatile("cp.async.commit_group;"); }
template <int N>
__device__ __forceinline__ void cpa_wait() {
    asm volatile("cp.async.wait_group %0;" :: "n"(N) : "memory");
}

__global__ __launch_bounds__(256, 2)
void doc_kernel(const float* __restrict__ dkeys) {
    extern __shared__ char dsm[];
    const int d = blockIdx.x;
    const int tid = threadIdx.x;
    const int w = tid >> 5;
    const int lane = tid & 31;
    const int c = w * 4 + (lane >> 3);
    const int bg = lane & 7;

    float* wmax = (float*)(dsm + 2 * STAGE_F * 4);
    const uint32_t sb = smem_u32(dsm);

    auto stage = [&](int s, int l) {
        const float* ksrc = dkeys + (((size_t)d * L_ + l) * C_) * R_;
        uint32_t kdst = sb + s * (STAGE_F * 4);
#pragma unroll
        for (int i = 0; i < 8; i++) {
            int id = tid + i * 256;
            int cc = id >> 6, off = id & 63;
            cpa16(kdst + (cc * 260 + off * 4) * 4, ksrc + id * 4);
        }
        uint32_t qdst = kdst + K_STAGE_F * 4;
#pragma unroll
        for (int i = 0; i < 4; i++) {
            int id = tid + i * 256;
            int bb = id >> 6, off = id & 63;
            cpa16(qdst + (bb * 260 + off * 4) * 4, g_qvec + (bb * L_ + l) * R_ + off * 4);
        }
        cpa_commit();
    };

    stage(0, 0);

    float acc = 0.0f;
    for (int l = 0; l < L_; l++) {
        const int s = l & 1;
        if (l < L_ - 1) stage(s ^ 1, l + 1);
        if (l < L_ - 1) cpa_wait<1>(); else cpa_wait<0>();
        __syncthreads();

        const float* kb = (const float*)(dsm + s * (STAGE_F * 4));
        const float* qb = kb + K_STAGE_F;
        const float4* kp = (const float4*)(kb + c * 260);
        const float4* q0 = (const float4*)(qb + bg * 260);
        const float4* q1 = (const float4*)(qb + (bg + 8) * 260);

        float dot0 = 0.0f, dot1 = 0.0f, nn = 0.0f;
#pragma unroll 8
        for (int r4 = 0; r4 < 64; r4++) {
            float4 k = kp[r4];
            float4 a = q0[r4];
            float4 q = q1[r4];
            dot0 = fmaf(k.x, a.x, dot0); dot0 = fmaf(k.y, a.y, dot0);
            dot0 = fmaf(k.z, a.z, dot0); dot0 = fmaf(k.w, a.w, dot0);
            dot1 = fmaf(k.x, q.x, dot1); dot1 = fmaf(k.y, q.y, dot1);
            dot1 = fmaf(k.z, q.z, dot1); dot1 = fmaf(k.w, q.w, dot1);
            nn   = fmaf(k.x, k.x, nn);   nn   = fmaf(k.y, k.y, nn);
            nn   = fmaf(k.z, k.z, nn);   nn   = fmaf(k.w, k.w, nn);
        }
        float inv = 1.0f / fmaxf(sqrtf(nn), 1e-12f);
        float s0 = dot0 * inv;
        float s1 = dot1 * inv;
        s0 = fmaxf(s0, __shfl_xor_sync(0xffffffffu, s0, 8));
        s0 = fmaxf(s0, __shfl_xor_sync(0xffffffffu, s0, 16));
        s1 = fmaxf(s1, __shfl_xor_sync(0xffffffffu, s1, 8));
        s1 = fmaxf(s1, __shfl_xor_sync(0xffffffffu, s1, 16));
        if (lane < 8) { wmax[w * 16 + lane] = s0; wmax[w * 16 + lane + 8] = s1; }
        __syncthreads();
        if (tid < 16) {
            float mx = wmax[tid];
#pragma unroll
            for (int ww = 1; ww < 8; ww++) mx = fmaxf(mx, wmax[ww * 16 + tid]);
            acc += mx;
        }
        __syncthreads();
    }
    if (tid < 16) g_scores[tid * D_ + d] = acc * (1.0f / (float)L_);
}

// ---------------------------------------------------------------------------
// topk_kernel: exact top-16 (desc, lower index wins ties)
// ---------------------------------------------------------------------------
__global__ void topk_kernel(float* __restrict__ out, int half) {
    const int b = blockIdx.x;
    const int t = threadIdx.x;
    __shared__ float sv[D_];
    __shared__ float rv[256];
    __shared__ int   ri[256];

    for (int i = t; i < D_; i += 256) sv[i] = g_scores[b * D_ + i];
    __syncthreads();

    for (int k = 0; k < TOPK_; k++) {
        float bv = -CUDART_INF_F;
        int   bi = 0x7fffffff;
        for (int i = t; i < D_; i += 256) {
            float v = sv[i];
            if (v > bv || (v == bv && i < bi)) { bv = v; bi = i; }
        }
        rv[t] = bv; ri[t] = bi;
        __syncthreads();
        for (int s = 128; s > 0; s >>= 1) {
            if (t < s) {
                float ov = rv[t + s]; int oi = ri[t + s];
                if (ov > rv[t] || (ov == rv[t] && oi < ri[t])) { rv[t] = ov; ri[t] = oi; }
            }
            __syncthreads();
        }
        if (t == 0) {
            out[b * TOPK_ + k]        = rv[0];
            out[half + b * TOPK_ + k] = (float)ri[0];
            sv[ri[0]] = -CUDART_INF_F;
        }
        __syncthreads();
    }
}

extern "C" void kernel_launch(void* const* d_in, const int* in_sizes, int n_in,
                              void* d_out, int out_size) {
    const float* qhs = (const float*)d_in[0];
    const float* wq  = (const float*)d_in[1];
    const float* dk  = (const float*)d_in[2];
    float* out = (float*)d_out;

    cudaFuncSetAttribute(proj_kernel, cudaFuncAttributeMaxDynamicSharedMemorySize, PROJ_SMEM);
    cudaFuncSetAttribute(doc_kernel,  cudaFuncAttributeMaxDynamicSharedMemorySize, DOC_SMEM);

    init_kernel<<<B_ * L_, 256>>>();
    dim3 gp(B_ * L_, 2, 2);
    proj_kernel<<<gp, 256, PROJ_SMEM>>>(qhs, wq);
    norm_kernel<<<B_ * L_, 256>>>();
    doc_kernel<<<D_, 256, DOC_SMEM>>>(dk);
    topk_kernel<<<B_, 256>>>(out, out_size / 2);
}

// round 5
// speedup vs baseline: 2.0129x; 1.8356x over previous
#include <cuda_runtime.h>
#include <cuda_fp16.h>
#include <math_constants.h>
#include <cstdint>

#define B_   16
#define L_   18
#define SQ_  256
#define H_   2560
#define R_   256
#define D_   2048
#define C_   32
#define TOPK_ 16

// ---------------- scratch (no allocs allowed) ----------------
__device__ unsigned int g_qenc[B_ * L_ * R_];
__device__ float        g_qvec[B_ * L_ * R_];
__device__ float        g_scores[B_ * D_];
// wq split into fp16 main/corr, fragment order: [l][stage 80][8192 u32]
//   [0..4095] = main (ntg*2+kc)*32*2 + ..., [4096..8191] = corr
__device__ uint32_t     g_wsplit[(size_t)L_ * 80 * 8192];

// Order-preserving float <-> uint encoding for atomicMax
__device__ __forceinline__ unsigned enc_f(float f) {
    unsigned u = __float_as_uint(f);
    return (u & 0x80000000u) ? ~u : (u | 0x80000000u);
}
__device__ __forceinline__ float dec_f(unsigned u) {
    unsigned b = (u & 0x80000000u) ? (u & 0x7FFFFFFFu) : ~u;
    return __uint_as_float(b);
}

// split x,y into fp16 main pair + fp16 residual pair (packed fp16x2)
__device__ __forceinline__ void split2(float x, float y, uint32_t& m, uint32_t& c) {
    __half hx = __float2half_rn(x);
    __half hy = __float2half_rn(y);
    float rx = x - __half2float(hx);
    float ry = y - __half2float(hy);
    __half2 hm = __halves2half2(hx, hy);
    __half2 hc = __halves2half2(__float2half_rn(rx), __float2half_rn(ry));
    m = *reinterpret_cast<uint32_t*>(&hm);
    c = *reinterpret_cast<uint32_t*>(&hc);
}

#define MMA_F16(Cv, Av, Bv)                                                    \
    asm volatile("mma.sync.aligned.m16n8k16.row.col.f32.f16.f16.f32 "          \
                 "{%0,%1,%2,%3}, {%4,%5,%6,%7}, {%8,%9}, {%0,%1,%2,%3};"       \
                 : "+f"(Cv[0]), "+f"(Cv[1]), "+f"(Cv[2]), "+f"(Cv[3])          \
                 : "r"(Av[0]), "r"(Av[1]), "r"(Av[2]), "r"(Av[3]),             \
                   "r"(Bv[0]), "r"(Bv[1]))

__device__ __forceinline__ uint32_t smem_u32(const void* p) {
    uint32_t a;
    asm("{ .reg .u64 t; cvta.to.shared.u64 t, %1; cvt.u32.u64 %0, t; }"
        : "=r"(a) : "l"(p));
    return a;
}
__device__ __forceinline__ void cpa16(uint32_t saddr, const void* g) {
    asm volatile("cp.async.cg.shared.global [%0], [%1], 16;" :: "r"(saddr), "l"(g));
}
__device__ __forceinline__ void cpa_commit() { asm volatile("cp.async.commit_group;"); }
template <int N>
__device__ __forceinline__ void cpa_wait() {
    asm volatile("cp.async.wait_group %0;" :: "n"(N) : "memory");
}

// ---------------------------------------------------------------------------
// init: reset encoded-max buffer
// ---------------------------------------------------------------------------
__global__ void init_kernel() {
    g_qenc[blockIdx.x * 256 + threadIdx.x] = 0u;
}

// ---------------------------------------------------------------------------
// wprep: split wq*64 into fp16 main/corr in B-fragment order.
// One block per (l, stage). The *64 scale cancels in L2-normalization.
// ---------------------------------------------------------------------------
__global__ __launch_bounds__(256) void wprep_kernel(const float* __restrict__ wq) {
    const int lt = blockIdx.x;          // l*80 + t
    const int l = lt / 80, t = lt % 80;
    const int tid = threadIdx.x;
    uint32_t* dst = g_wsplit + (size_t)lt * 8192;
    const float* src = wq + (size_t)l * R_ * H_ + t * 32;
#pragma unroll
    for (int i = 0; i < 8; i++) {
        int ch = tid + i * 256;         // 0..2047
        int r  = ch >> 3;               // 0..255
        int k4 = (ch & 7) << 2;         // 0..28
        float4 v = *(const float4*)(src + (size_t)r * H_ + k4);
        v.x *= 64.f; v.y *= 64.f; v.z *= 64.f; v.w *= 64.f;
        int ntg = r >> 3, g = r & 7;
        int kc = k4 >> 4, kk16 = k4 & 15;
        int tq = (kk16 >> 1) & 3, khalf = kk16 >> 3;
        uint32_t m0, c0, m1, c1;
        split2(v.x, v.y, m0, c0);
        split2(v.z, v.w, m1, c1);
        int base = (ntg * 2 + kc) * 32 + g * 4;
        dst[(base + tq) * 2 + khalf]            = m0;
        dst[4096 + (base + tq) * 2 + khalf]     = c0;
        dst[(base + tq + 1) * 2 + khalf]        = m1;
        dst[4096 + (base + tq + 1) * 2 + khalf] = c1;
    }
}

// ---------------------------------------------------------------------------
// proj_kernel: per (b,l): C[s,r] = qhs[b,l,s,:] . wq[l,r,:]
// fp16 3-term split, single fp32 accumulator. CTA tile 128(s) x 256(r).
// 8 warps: wm = s-half (64 rows), wn = r-quarter (64 cols = 8 nt).
// A (qhs) converted in-CTA to fragment-order smem; B cp.async from g_wsplit.
// Stage layout (u32): [0:2048) Amain [2048:4096) Acorr [4096:8192) Bmain
// [8192:12288) Bcorr. 48KB/stage, 2 stages.
// ---------------------------------------------------------------------------
#define PSTG_U32  12288
#define PROJ_SMEM (2 * PSTG_U32 * 4)    // 96 KB

__global__ __launch_bounds__(256)
void proj_kernel(const float* __restrict__ qhs) {
    extern __shared__ uint32_t sm[];
    const int tid  = threadIdx.x;
    const int lane = tid & 31;
    const int warp = tid >> 5;
    const int wm   = warp >> 2;     // 0..1
    const int wn   = warp & 3;      // 0..3

    const int bl = blockIdx.x;      // b*L + l
    const int sT = blockIdx.y;      // 0..1
    const int l  = bl % L_;

    const float* Ag = qhs + ((size_t)bl * SQ_ + (size_t)sT * 128) * H_;
    const uint32_t* Wg = g_wsplit + (size_t)l * 80 * 8192;
    const uint32_t sbase = smem_u32(sm);

    float acc[4][8][4];
#pragma unroll
    for (int i = 0; i < 4; i++)
#pragma unroll
        for (int j = 0; j < 8; j++)
#pragma unroll
            for (int k = 0; k < 4; k++) acc[i][j][k] = 0.0f;

    float4 pa[4];

    auto ldA = [&](int t) {
#pragma unroll
        for (int i = 0; i < 4; i++) {
            int ch = tid + i * 256;           // 0..1023
            int row = ch >> 3;                // 0..127
            int k4 = (ch & 7) << 2;
            pa[i] = *(const float4*)(Ag + (size_t)row * H_ + t * 32 + k4);
        }
    };
    auto stA = [&](int s) {
        uint32_t* base = sm + s * PSTG_U32;
#pragma unroll
        for (int i = 0; i < 4; i++) {
            int ch = tid + i * 256;
            int row = ch >> 3;
            int k4 = (ch & 7) << 2;
            int mt = row >> 4, r16 = row & 15;
            int g = r16 & 7, half = r16 >> 3;
            int kc = k4 >> 4, kk16 = k4 & 15;
            int tq = (kk16 >> 1) & 3, khalf = kk16 >> 3;
            int j = half + 2 * khalf;
            uint32_t m0, c0, m1, c1;
            split2(pa[i].x, pa[i].y, m0, c0);
            split2(pa[i].z, pa[i].w, m1, c1);
            int ab = (mt * 2 + kc) * 32 + g * 4;
            base[(ab + tq) * 4 + j]            = m0;
            base[2048 + (ab + tq) * 4 + j]     = c0;
            base[(ab + tq + 1) * 4 + j]        = m1;
            base[2048 + (ab + tq + 1) * 4 + j] = c1;
        }
    };
    auto prefB = [&](int t, int s) {
        uint32_t dstb = sbase + (s * PSTG_U32 + 4096) * 4;
        const uint32_t* gsrc = Wg + (size_t)t * 8192;
#pragma unroll
        for (int i = 0; i < 8; i++) {
            int off = (tid + i * 256) * 4;      // u32 offset, 16B chunks
            cpa16(dstb + off * 4, gsrc + off);
        }
        cpa_commit();
    };

    prefB(0, 0);
    ldA(0);
    stA(0);
    cpa_wait<0>();
    __syncthreads();

    for (int t = 0; t < 80; t++) {
        const int s = t & 1;
        if (t < 79) { prefB(t + 1, s ^ 1); ldA(t + 1); }

        const uint32_t* A_ = sm + s * PSTG_U32;
        const uint32_t* Bm = A_ + 4096;
        const uint32_t* Bc = A_ + 8192;

#pragma unroll
        for (int kc = 0; kc < 2; kc++) {
            uint32_t ah[4][4], ac[4][4];
#pragma unroll
            for (int mt = 0; mt < 4; mt++) {
                int mtg = wm * 4 + mt;
                *(uint4*)ah[mt] = *(const uint4*)(A_ + ((mtg * 2 + kc) * 32 + lane) * 4);
                *(uint4*)ac[mt] = *(const uint4*)(A_ + 2048 + ((mtg * 2 + kc) * 32 + lane) * 4);
            }
#pragma unroll
            for (int nt = 0; nt < 8; nt++) {
                int ntg = wn * 8 + nt;
                uint2 bm = *(const uint2*)(Bm + ((ntg * 2 + kc) * 32 + lane) * 2);
                uint2 bc = *(const uint2*)(Bc + ((ntg * 2 + kc) * 32 + lane) * 2);
                uint32_t bmv[2] = { bm.x, bm.y };
                uint32_t bcv[2] = { bc.x, bc.y };
#pragma unroll
                for (int mt = 0; mt < 4; mt++) MMA_F16(acc[mt][nt], ah[mt], bmv);
#pragma unroll
                for (int mt = 0; mt < 4; mt++) MMA_F16(acc[mt][nt], ah[mt], bcv);
#pragma unroll
                for (int mt = 0; mt < 4; mt++) MMA_F16(acc[mt][nt], ac[mt], bmv);
            }
        }

        if (t < 79) { stA(s ^ 1); cpa_wait<0>(); }
        __syncthreads();
    }

    // ---- epilogue: max over s rows, shuffle-reduce, atomicMax ----
    unsigned* qe = g_qenc + (size_t)bl * R_;
#pragma unroll
    for (int nt = 0; nt < 8; nt++) {
        float v0 = -CUDART_INF_F, v1 = -CUDART_INF_F;
#pragma unroll
        for (int mt = 0; mt < 4; mt++) {
            v0 = fmaxf(v0, fmaxf(acc[mt][nt][0], acc[mt][nt][2]));
            v1 = fmaxf(v1, fmaxf(acc[mt][nt][1], acc[mt][nt][3]));
        }
#pragma unroll
        for (int o = 4; o < 32; o <<= 1) {
            v0 = fmaxf(v0, __shfl_xor_sync(0xffffffffu, v0, o));
            v1 = fmaxf(v1, __shfl_xor_sync(0xffffffffu, v1, o));
        }
        if (lane < 4) {
            int col = (wn * 8 + nt) * 8 + lane * 2;
            atomicMax(&qe[col],     enc_f(v0));
            atomicMax(&qe[col + 1], enc_f(v1));
        }
    }
}

// ---------------------------------------------------------------------------
// norm_kernel: decode + L2-normalize q over R (one block per (b,l))
// ---------------------------------------------------------------------------
__global__ void norm_kernel() {
    const int blk = blockIdx.x;
    const int t = threadIdx.x;
    float v = dec_f(g_qenc[blk * R_ + t]);
    float s = v * v;
#pragma unroll
    for (int o = 16; o > 0; o >>= 1) s += __shfl_xor_sync(0xffffffffu, s, o);
    __shared__ float ws[8];
    if ((t & 31) == 0) ws[t >> 5] = s;
    __syncthreads();
    float tot = 0.0f;
#pragma unroll
    for (int i = 0; i < 8; i++) tot += ws[i];
    g_qvec[blk * R_ + t] = v / fmaxf(sqrtf(tot), 1e-12f);
}

// ---------------------------------------------------------------------------
// doc_kernel: cp.async-staged k + q tiles, double-buffered per layer.
// ---------------------------------------------------------------------------
#define K_STAGE_F  (C_ * 260)
#define Q_STAGE_F  (B_ * 260)
#define STAGE_F    (K_STAGE_F + Q_STAGE_F)
#define DOC_SMEM   (2 * STAGE_F * 4 + 512)

__global__ __launch_bounds__(256, 2)
void doc_kernel(const float* __restrict__ dkeys) {
    extern __shared__ char dsm[];
    const int d = blockIdx.x;
    const int tid = threadIdx.x;
    const int w = tid >> 5;
    const int lane = tid & 31;
    const int c = w * 4 + (lane >> 3);
    const int bg = lane & 7;

    float* wmax = (float*)(dsm + 2 * STAGE_F * 4);
    const uint32_t sb = smem_u32(dsm);

    auto stage = [&](int s, int l) {
        const float* ksrc = dkeys + (((size_t)d * L_ + l) * C_) * R_;
        uint32_t kdst = sb + s * (STAGE_F * 4);
#pragma unroll
        for (int i = 0; i < 8; i++) {
            int id = tid + i * 256;
            int cc = id >> 6, off = id & 63;
            cpa16(kdst + (cc * 260 + off * 4) * 4, ksrc + id * 4);
        }
        uint32_t qdst = kdst + K_STAGE_F * 4;
#pragma unroll
        for (int i = 0; i < 4; i++) {
            int id = tid + i * 256;
            int bb = id >> 6, off = id & 63;
            cpa16(qdst + (bb * 260 + off * 4) * 4, g_qvec + (bb * L_ + l) * R_ + off * 4);
        }
        cpa_commit();
    };

    stage(0, 0);

    float acc = 0.0f;
    for (int l = 0; l < L_; l++) {
        const int s = l & 1;
        if (l < L_ - 1) stage(s ^ 1, l + 1);
        if (l < L_ - 1) cpa_wait<1>(); else cpa_wait<0>();
        __syncthreads();

        const float* kb = (const float*)(dsm + s * (STAGE_F * 4));
        const float* qb = kb + K_STAGE_F;
        const float4* kp = (const float4*)(kb + c * 260);
        const float4* q0 = (const float4*)(qb + bg * 260);
        const float4* q1 = (const float4*)(qb + (bg + 8) * 260);

        float dot0 = 0.0f, dot1 = 0.0f, nn = 0.0f;
#pragma unroll 8
        for (int r4 = 0; r4 < 64; r4++) {
            float4 k = kp[r4];
            float4 a = q0[r4];
            float4 q = q1[r4];
            dot0 = fmaf(k.x, a.x, dot0); dot0 = fmaf(k.y, a.y, dot0);
            dot0 = fmaf(k.z, a.z, dot0); dot0 = fmaf(k.w, a.w, dot0);
            dot1 = fmaf(k.x, q.x, dot1); dot1 = fmaf(k.y, q.y, dot1);
            dot1 = fmaf(k.z, q.z, dot1); dot1 = fmaf(k.w, q.w, dot1);
            nn   = fmaf(k.x, k.x, nn);   nn   = fmaf(k.y, k.y, nn);
            nn   = fmaf(k.z, k.z, nn);   nn   = fmaf(k.w, k.w, nn);
        }
        float inv = 1.0f / fmaxf(sqrtf(nn), 1e-12f);
        float s0 = dot0 * inv;
        float s1 = dot1 * inv;
        s0 = fmaxf(s0, __shfl_xor_sync(0xffffffffu, s0, 8));
        s0 = fmaxf(s0, __shfl_xor_sync(0xffffffffu, s0, 16));
        s1 = fmaxf(s1, __shfl_xor_sync(0xffffffffu, s1, 8));
        s1 = fmaxf(s1, __shfl_xor_sync(0xffffffffu, s1, 16));
        if (lane < 8) { wmax[w * 16 + lane] = s0; wmax[w * 16 + lane + 8] = s1; }
        __syncthreads();
        if (tid < 16) {
            float mx = wmax[tid];
#pragma unroll
            for (int ww = 1; ww < 8; ww++) mx = fmaxf(mx, wmax[ww * 16 + tid]);
            acc += mx;
        }
        __syncthreads();
    }
    if (tid < 16) g_scores[tid * D_ + d] = acc * (1.0f / (float)L_);
}

// ---------------------------------------------------------------------------
// topk_kernel: exact top-16 (desc, lower index wins ties)
// ---------------------------------------------------------------------------
__global__ void topk_kernel(float* __restrict__ out, int half) {
    const int b = blockIdx.x;
    const int t = threadIdx.x;
    __shared__ float sv[D_];
    __shared__ float rv[256];
    __shared__ int   ri[256];

    for (int i = t; i < D_; i += 256) sv[i] = g_scores[b * D_ + i];
    __syncthreads();

    for (int k = 0; k < TOPK_; k++) {
        float bv = -CUDART_INF_F;
        int   bi = 0x7fffffff;
        for (int i = t; i < D_; i += 256) {
            float v = sv[i];
            if (v > bv || (v == bv && i < bi)) { bv = v; bi = i; }
        }
        rv[t] = bv; ri[t] = bi;
        __syncthreads();
        for (int s = 128; s > 0; s >>= 1) {
            if (t < s) {
                float ov = rv[t + s]; int oi = ri[t + s];
                if (ov > rv[t] || (ov == rv[t] && oi < ri[t])) { rv[t] = ov; ri[t] = oi; }
            }
            __syncthreads();
        }
        if (t == 0) {
            out[b * TOPK_ + k]        = rv[0];
            out[half + b * TOPK_ + k] = (float)ri[0];
            sv[ri[0]] = -CUDART_INF_F;
        }
        __syncthreads();
    }
}

extern "C" void kernel_launch(void* const* d_in, const int* in_sizes, int n_in,
                              void* d_out, int out_size) {
    const float* qhs = (const float*)d_in[0];
    const float* wq  = (const float*)d_in[1];
    const float* dk  = (const float*)d_in[2];
    float* out = (float*)d_out;

    cudaFuncSetAttribute(proj_kernel, cudaFuncAttributeMaxDynamicSharedMemorySize, PROJ_SMEM);
    cudaFuncSetAttribute(doc_kernel,  cudaFuncAttributeMaxDynamicSharedMemorySize, DOC_SMEM);

    init_kernel<<<B_ * L_, 256>>>();
    wprep_kernel<<<L_ * 80, 256>>>(wq);
    dim3 gp(B_ * L_, 2);
    proj_kernel<<<gp, 256, PROJ_SMEM>>>(qhs);
    norm_kernel<<<B_ * L_, 256>>>();
    doc_kernel<<<D_, 256, DOC_SMEM>>>(dk);
    topk_kernel<<<B_, 256>>>(out, out_size / 2);
}